// round 6
// baseline (speedup 1.0000x reference)
#include <cuda_runtime.h>
#include <cuda_bf16.h>
#include <cstdint>

// Problem constants
#define NB 2        // B
#define LL 16       // L
#define NN 10000    // N
#define FIN 8
#define HH 64       // H
#define PP 12       // P
#define EE 80000    // E
// Only l = 14,15 feed out[:, :, -1]. Slot s = b*2 + (l-14); row = [n][s][64].
#define SLOTS 4
#define ROWF (SLOTS * HH)   // 256 floats per node row
#define CAP 64              // per-node edge bucket capacity (max deg ~30)

// Scratch
__device__ __align__(16) float g_h[(size_t)NN * ROWF];
__device__ __align__(16) float g_agg[(size_t)NN * ROWF];   // relu'd aggregate
__device__ int g_cnt[NN];                                  // zero-init; K2 cleans
__device__ __align__(8) int2 g_edge[(size_t)NN * CAP];     // {col, val_bits}

// ---------------------------------------------------------------------------
// K1: one warp per node: h[n,s,:] = relu(x[b,l,n,:]@W_in + b_in), s=0..3
//     (l in {14,15}); plus edge binning on the first EE threads.
// ---------------------------------------------------------------------------
__global__ void k_proj_bin(const float* __restrict__ x,
                           const float* __restrict__ W_in,
                           const float* __restrict__ b_in,
                           const int* __restrict__ row,
                           const int* __restrict__ col,
                           const float* __restrict__ vals) {
    __shared__ float sW[FIN * HH];
    __shared__ float sb[HH];
    int tid = threadIdx.x;
    int gid = blockIdx.x * blockDim.x + tid;

    if (gid < EE) {
        int r = __ldg(row + gid);
        int rank = atomicAdd(&g_cnt[r], 1);
        if (rank < CAP)
            g_edge[(size_t)r * CAP + rank] =
                make_int2(__ldg(col + gid), __float_as_int(__ldg(vals + gid)));
    }

    for (int i = tid; i < FIN * HH; i += blockDim.x) sW[i] = W_in[i];
    if (tid < HH) sb[tid] = b_in[tid];
    __syncthreads();

    int n = blockIdx.x * 8 + (tid >> 5);   // exactly 10000
    int lane = tid & 31;

    #pragma unroll
    for (int s = 0; s < SLOTS; s++) {
        int b = s >> 1;
        int l = 14 + (s & 1);
        const float4* xr = reinterpret_cast<const float4*>(
            x + (((size_t)b * LL + l) * NN + n) * FIN);
        float4 x0 = __ldg(xr);       // warp-broadcast 32B row
        float4 x1 = __ldg(xr + 1);
        float xv[8] = {x0.x, x0.y, x0.z, x0.w, x1.x, x1.y, x1.z, x1.w};

        float* hrow = g_h + ((size_t)n * SLOTS + s) * HH;
        #pragma unroll
        for (int rep = 0; rep < 2; rep++) {
            int hh = lane + rep * 32;
            float acc = sb[hh];
            #pragma unroll
            for (int f = 0; f < 8; f++) acc = fmaf(xv[f], sW[f * HH + hh], acc);
            hrow[hh] = fmaxf(acc, 0.0f);
        }
    }
}

// ---------------------------------------------------------------------------
// K2: gather, one warp per node, 8-edge software pipeline.
// Edge list loaded lane-parallel (one LDG.64); lanes >= deg carry (0, 0.0f)
// so padded edges read node-0's row (L1-hot) with v = 0 -> branch-free.
// Per 8-edge group: 8 shfl pairs, then 16 independent LDG.128, then 128 FMA.
// ---------------------------------------------------------------------------
__global__ void k_gather() {
    int n = blockIdx.x * 8 + (threadIdx.x >> 5);   // exactly 10000 warps
    int lane = threadIdx.x & 31;

    int deg = g_cnt[n];
    if (deg > CAP) deg = CAP;
    if (lane == 0) g_cnt[n] = 0;                   // self-clean
    const int2* ep = g_edge + (size_t)n * CAP;

    float4 a0 = make_float4(0.f, 0.f, 0.f, 0.f);
    float4 a1 = make_float4(0.f, 0.f, 0.f, 0.f);

    for (int base = 0; base < deg; base += 32) {
        int idx = base + lane;
        int2 e = make_int2(0, 0);
        if (idx < deg) e = __ldg(ep + idx);
        int cnt = min(32, deg - base);

        for (int k0 = 0; k0 < cnt; k0 += 8) {
            int   c[8];
            float v[8];
            #pragma unroll
            for (int j = 0; j < 8; j++) {
                int kk = (k0 + j) & 31;
                c[j] = __shfl_sync(0xffffffffu, e.x, kk);
                v[j] = __int_as_float(__shfl_sync(0xffffffffu, e.y, kk));
            }
            float4 h0[8], h1[8];
            #pragma unroll
            for (int j = 0; j < 8; j++) {
                const float4* hp =
                    reinterpret_cast<const float4*>(g_h + (size_t)c[j] * ROWF);
                h0[j] = __ldg(hp + lane);
                h1[j] = __ldg(hp + lane + 32);
            }
            #pragma unroll
            for (int j = 0; j < 8; j++) {
                a0.x = fmaf(h0[j].x, v[j], a0.x);
                a0.y = fmaf(h0[j].y, v[j], a0.y);
                a0.z = fmaf(h0[j].z, v[j], a0.z);
                a0.w = fmaf(h0[j].w, v[j], a0.w);
                a1.x = fmaf(h1[j].x, v[j], a1.x);
                a1.y = fmaf(h1[j].y, v[j], a1.y);
                a1.z = fmaf(h1[j].z, v[j], a1.z);
                a1.w = fmaf(h1[j].w, v[j], a1.w);
            }
        }
    }

    float4* ap = reinterpret_cast<float4*>(g_agg + (size_t)n * ROWF);
    ap[lane] = make_float4(fmaxf(a0.x, 0.f), fmaxf(a0.y, 0.f),
                           fmaxf(a0.z, 0.f), fmaxf(a0.w, 0.f));
    ap[lane + 32] = make_float4(fmaxf(a1.x, 0.f), fmaxf(a1.y, 0.f),
                                fmaxf(a1.z, 0.f), fmaxf(a1.w, 0.f));
}

// ---------------------------------------------------------------------------
// K3: final stage, 4 nodes (8 (node,b) pairs) per warp, 8 warps/block.
// ---------------------------------------------------------------------------
#define K3_WARPS 8
#define K3_NPW 4
#define K3_NODES_BLK (K3_WARPS * K3_NPW)      // 32
#define K3_GRID ((NN + K3_NODES_BLK - 1) / K3_NODES_BLK)   // 313

#define SM3_WT 0
#define SM3_SU (SM3_WT + 32 * 64 * 16)                     // 32768
#define SM3_WO (SM3_SU + K3_WARPS * 8 * 32 * 16)           // +32768 = 65536
#define SM3_BT (SM3_WO + PP * 64 * 4)                      // +3072  = 68608
#define SM3_BO (SM3_BT + 64 * 4)                           // +256   = 68864
#define SM3_TOT (SM3_BO + 64)                              //        = 68928

__global__ void __launch_bounds__(K3_WARPS * 32, 2)
k_final(const float* __restrict__ W_tcn,
        const float* __restrict__ b_tcn,
        const float* __restrict__ W_out,
        const float* __restrict__ b_out,
        float* __restrict__ out) {
    extern __shared__ char dsm[];
    float4 (*sWt4)[64] = reinterpret_cast<float4(*)[64]>(dsm + SM3_WT);
    float4 (*su4)[8][32] = reinterpret_cast<float4(*)[8][32]>(dsm + SM3_SU);
    float*  sWoT = reinterpret_cast<float*>(dsm + SM3_WO);
    float*  sbt  = reinterpret_cast<float*>(dsm + SM3_BT);
    float*  sbo  = reinterpret_cast<float*>(dsm + SM3_BO);

    int tid = threadIdx.x;
    int nthr = K3_WARPS * 32;
    for (int idx = tid; idx < 32 * 64; idx += nthr) {
        int ip = idx >> 6, o = idx & 63;
        const float* wb = W_tcn + o * 192 + ip * 6;   // i = 2ip, taps 0,1
        sWt4[ip][o] = make_float4(wb[0], wb[1], wb[3], wb[4]);
    }
    for (int idx = tid; idx < PP * 64; idx += nthr) {
        int p = idx >> 6, o = idx & 63;
        sWoT[p * 64 + o] = W_out[o * PP + p];
    }
    if (tid < 64) sbt[tid] = b_tcn[tid];
    if (tid < PP) sbo[tid] = b_out[tid];
    __syncthreads();

    int w = tid >> 5, lane = tid & 31;
    int nBase = (blockIdx.x * K3_WARPS + w) * K3_NPW;

    int tap = (lane >> 4) & 1;
    int hb8 = (lane & 15) * 8;
    #pragma unroll
    for (int m = 0; m < K3_NPW; m++) {
        int node = nBase + m;
        int nd = node < NN ? node : NN - 1;
        const float4* ar = reinterpret_cast<const float4*>(g_agg + (size_t)nd * ROWF);
        float4 r0 = __ldg(ar + lane);        // b = 0 data
        float4 r1 = __ldg(ar + lane + 32);   // b = 1 data
        float* d0 = reinterpret_cast<float*>(&su4[w][m * 2 + 0][0]);
        float* d1 = reinterpret_cast<float*>(&su4[w][m * 2 + 1][0]);
        d0[hb8 + 0 + tap] = r0.x;  d0[hb8 + 2 + tap] = r0.y;
        d0[hb8 + 4 + tap] = r0.z;  d0[hb8 + 6 + tap] = r0.w;
        d1[hb8 + 0 + tap] = r1.x;  d1[hb8 + 2 + tap] = r1.y;
        d1[hb8 + 4 + tap] = r1.z;  d1[hb8 + 6 + tap] = r1.w;
    }
    __syncwarp();

    float z0[8], z1[8];
    #pragma unroll
    for (int pp = 0; pp < 8; pp++) { z0[pp] = sbt[lane]; z1[pp] = sbt[lane + 32]; }
    #pragma unroll 4
    for (int ip = 0; ip < 32; ip++) {
        float4 wA = sWt4[ip][lane];
        float4 wB = sWt4[ip][lane + 32];
        #pragma unroll
        for (int pp = 0; pp < 8; pp++) {
            float4 u = su4[w][pp][ip];
            z0[pp] = fmaf(wA.x, u.x, fmaf(wA.y, u.y,
                     fmaf(wA.z, u.z, fmaf(wA.w, u.w, z0[pp]))));
            z1[pp] = fmaf(wB.x, u.x, fmaf(wB.y, u.y,
                     fmaf(wB.z, u.z, fmaf(wB.w, u.w, z1[pp]))));
        }
    }
    __syncwarp();
    #pragma unroll
    for (int pp = 0; pp < 8; pp++) {
        float* zf = reinterpret_cast<float*>(&su4[w][pp][0]);
        zf[lane]      = fmaxf(z0[pp], 0.0f);
        zf[lane + 32] = fmaxf(z1[pp], 0.0f);
    }
    __syncwarp();

    #pragma unroll
    for (int r = 0; r < 3; r++) {
        int q = lane + r * 32;               // 0..95
        int pp = q / PP;
        int p  = q - pp * PP;
        float y = sbo[p];
        const float4* z4 = &su4[w][pp][0];
        const float4* w4 = reinterpret_cast<const float4*>(sWoT + p * 64);
        #pragma unroll 4
        for (int oc = 0; oc < 16; oc++) {
            float4 zz = z4[oc];
            float4 ww = w4[oc];
            y = fmaf(zz.x, ww.x, fmaf(zz.y, ww.y,
                fmaf(zz.z, ww.z, fmaf(zz.w, ww.w, y))));
        }
        int node = nBase + (pp >> 1);
        int b = pp & 1;
        if (node < NN)
            out[((size_t)b * PP + p) * NN + node] = y;
    }
}

// ---------------------------------------------------------------------------
extern "C" void kernel_launch(void* const* d_in, const int* in_sizes, int n_in,
                              void* d_out, int out_size) {
    const float* x     = (const float*)d_in[0];
    const int*   row   = (const int*)  d_in[1];
    const int*   col   = (const int*)  d_in[2];
    const float* vals  = (const float*)d_in[3];
    const float* W_in  = (const float*)d_in[4];
    const float* b_in  = (const float*)d_in[5];
    const float* W_tcn = (const float*)d_in[6];
    const float* b_tcn = (const float*)d_in[7];
    const float* W_out = (const float*)d_in[8];
    const float* b_out = (const float*)d_in[9];
    float* out = (float*)d_out;

    static bool attr_set = false;
    if (!attr_set) {
        cudaFuncSetAttribute(k_final,
                             cudaFuncAttributeMaxDynamicSharedMemorySize, SM3_TOT);
        attr_set = true;
    }

    k_proj_bin<<<1250, 256>>>(x, W_in, b_in, row, col, vals);
    k_gather<<<1250, 256>>>();
    k_final<<<K3_GRID, K3_WARPS * 32, SM3_TOT>>>(W_tcn, b_tcn, W_out, b_out, out);
}

// round 7
// speedup vs baseline: 1.2665x; 1.2665x over previous
#include <cuda_runtime.h>
#include <cuda_bf16.h>
#include <cstdint>

// Problem constants
#define NB 2        // B
#define LL 16       // L
#define NN 10000    // N
#define FIN 8
#define HH 64       // H
#define PP 12       // P
#define EE 80000    // E
// Only l = 14,15 feed out[:, :, -1]. Slot s = b*2 + (l-14); row = [n][s][64].
#define SLOTS 4
#define ROWF (SLOTS * HH)   // 256 floats per node row
#define CAP 64              // per-node edge bucket capacity (max deg ~35)

// Scratch
__device__ __align__(16) float g_h[(size_t)NN * ROWF];
__device__ __align__(16) float g_agg[(size_t)NN * ROWF];   // relu'd aggregate
__device__ int g_cnt[NN];                                  // zero-init; K2 cleans
__device__ __align__(8) int2 g_edge[(size_t)NN * CAP];     // {col, val_bits}

// ---------------------------------------------------------------------------
// K1: one warp per node: h[n,s,:] = relu(x[b,l,n,:]@W_in + b_in), s=0..3
//     (l in {14,15}); plus edge binning on the first EE threads.
// ---------------------------------------------------------------------------
__global__ void k_proj_bin(const float* __restrict__ x,
                           const float* __restrict__ W_in,
                           const float* __restrict__ b_in,
                           const int* __restrict__ row,
                           const int* __restrict__ col,
                           const float* __restrict__ vals) {
    __shared__ float sW[FIN * HH];
    __shared__ float sb[HH];
    int tid = threadIdx.x;
    int gid = blockIdx.x * blockDim.x + tid;

    if (gid < EE) {
        int r = __ldg(row + gid);
        int rank = atomicAdd(&g_cnt[r], 1);
        if (rank < CAP)
            g_edge[(size_t)r * CAP + rank] =
                make_int2(__ldg(col + gid), __float_as_int(__ldg(vals + gid)));
    }

    for (int i = tid; i < FIN * HH; i += blockDim.x) sW[i] = W_in[i];
    if (tid < HH) sb[tid] = b_in[tid];
    __syncthreads();

    int n = blockIdx.x * 8 + (tid >> 5);   // exactly 10000
    int lane = tid & 31;

    #pragma unroll
    for (int s = 0; s < SLOTS; s++) {
        int b = s >> 1;
        int l = 14 + (s & 1);
        const float4* xr = reinterpret_cast<const float4*>(
            x + (((size_t)b * LL + l) * NN + n) * FIN);
        float4 x0 = __ldg(xr);       // warp-broadcast 32B row
        float4 x1 = __ldg(xr + 1);
        float xv[8] = {x0.x, x0.y, x0.z, x0.w, x1.x, x1.y, x1.z, x1.w};

        float* hrow = g_h + ((size_t)n * SLOTS + s) * HH;
        #pragma unroll
        for (int rep = 0; rep < 2; rep++) {
            int hh = lane + rep * 32;
            float acc = sb[hh];
            #pragma unroll
            for (int f = 0; f < 8; f++) acc = fmaf(xv[f], sW[f * HH + hh], acc);
            hrow[hh] = fmaxf(acc, 0.0f);
        }
    }
}

// ---------------------------------------------------------------------------
// K2: gather (R5 structure — the best measured). One warp per node; edge list
// loaded lane-parallel, shfl-broadcast, 2-edge unroll with dual accumulators.
// ---------------------------------------------------------------------------
__global__ void k_gather() {
    int n = blockIdx.x * 8 + (threadIdx.x >> 5);   // exactly 10000 warps
    int lane = threadIdx.x & 31;

    int deg = g_cnt[n];
    if (deg > CAP) deg = CAP;
    if (lane == 0) g_cnt[n] = 0;                   // self-clean
    const int2* ep = g_edge + (size_t)n * CAP;

    float4 a0 = make_float4(0.f, 0.f, 0.f, 0.f);
    float4 a1 = make_float4(0.f, 0.f, 0.f, 0.f);
    float4 c0 = make_float4(0.f, 0.f, 0.f, 0.f);
    float4 c1 = make_float4(0.f, 0.f, 0.f, 0.f);

    for (int base = 0; base < deg; base += 32) {
        int idx = base + lane;
        int2 e = (idx < deg) ? __ldg(ep + idx) : make_int2(0, 0);
        int cnt = min(32, deg - base);
        int k = 0;
        for (; k + 1 < cnt; k += 2) {
            int   cA = __shfl_sync(0xffffffffu, e.x, k);
            float vA = __int_as_float(__shfl_sync(0xffffffffu, e.y, k));
            int   cB = __shfl_sync(0xffffffffu, e.x, k + 1);
            float vB = __int_as_float(__shfl_sync(0xffffffffu, e.y, k + 1));
            const float4* hpA = reinterpret_cast<const float4*>(g_h + (size_t)cA * ROWF);
            const float4* hpB = reinterpret_cast<const float4*>(g_h + (size_t)cB * ROWF);
            float4 pA0 = __ldg(hpA + lane);
            float4 pA1 = __ldg(hpA + lane + 32);
            float4 pB0 = __ldg(hpB + lane);
            float4 pB1 = __ldg(hpB + lane + 32);
            a0.x = fmaf(pA0.x, vA, a0.x); a0.y = fmaf(pA0.y, vA, a0.y);
            a0.z = fmaf(pA0.z, vA, a0.z); a0.w = fmaf(pA0.w, vA, a0.w);
            a1.x = fmaf(pA1.x, vA, a1.x); a1.y = fmaf(pA1.y, vA, a1.y);
            a1.z = fmaf(pA1.z, vA, a1.z); a1.w = fmaf(pA1.w, vA, a1.w);
            c0.x = fmaf(pB0.x, vB, c0.x); c0.y = fmaf(pB0.y, vB, c0.y);
            c0.z = fmaf(pB0.z, vB, c0.z); c0.w = fmaf(pB0.w, vB, c0.w);
            c1.x = fmaf(pB1.x, vB, c1.x); c1.y = fmaf(pB1.y, vB, c1.y);
            c1.z = fmaf(pB1.z, vB, c1.z); c1.w = fmaf(pB1.w, vB, c1.w);
        }
        if (k < cnt) {
            int   cA = __shfl_sync(0xffffffffu, e.x, k);
            float vA = __int_as_float(__shfl_sync(0xffffffffu, e.y, k));
            const float4* hpA = reinterpret_cast<const float4*>(g_h + (size_t)cA * ROWF);
            float4 pA0 = __ldg(hpA + lane);
            float4 pA1 = __ldg(hpA + lane + 32);
            a0.x = fmaf(pA0.x, vA, a0.x); a0.y = fmaf(pA0.y, vA, a0.y);
            a0.z = fmaf(pA0.z, vA, a0.z); a0.w = fmaf(pA0.w, vA, a0.w);
            a1.x = fmaf(pA1.x, vA, a1.x); a1.y = fmaf(pA1.y, vA, a1.y);
            a1.z = fmaf(pA1.z, vA, a1.z); a1.w = fmaf(pA1.w, vA, a1.w);
        }
    }

    float4* ap = reinterpret_cast<float4*>(g_agg + (size_t)n * ROWF);
    ap[lane] = make_float4(fmaxf(a0.x + c0.x, 0.f), fmaxf(a0.y + c0.y, 0.f),
                           fmaxf(a0.z + c0.z, 0.f), fmaxf(a0.w + c0.w, 0.f));
    ap[lane + 32] = make_float4(fmaxf(a1.x + c1.x, 0.f), fmaxf(a1.y + c1.y, 0.f),
                                fmaxf(a1.z + c1.z, 0.f), fmaxf(a1.w + c1.w, 0.f));
}

// ---------------------------------------------------------------------------
// K3: final stage — PERSISTENT: grid 148, 17 warps (544 thr), one 4-node
// group per warp (148*17*4 = 10064 >= 10000). Weights staged once per SM
// with coalesced gmem reads + LDS-side transpose.
// smem: sWt4[32][64] float4 (32KB) | su4[17][8][32] float4 (69.6KB, reused
// for z) | sWoT[12*64] | sbt[64] | sbo
// ---------------------------------------------------------------------------
#define K3_WARPS 17
#define K3_THREADS (K3_WARPS * 32)            // 544
#define K3_NPW 4

#define SM3_WT 0
#define SM3_SU (SM3_WT + 32 * 64 * 16)                     // 32768
#define SM3_WO (SM3_SU + K3_WARPS * 8 * 32 * 16)           // +69632 = 102400
#define SM3_BT (SM3_WO + PP * 64 * 4)                      // +3072  = 105472
#define SM3_BO (SM3_BT + 64 * 4)                           // +256   = 105728
#define SM3_TOT (SM3_BO + 64)                              //        = 105792

__global__ void __launch_bounds__(K3_THREADS, 1)
k_final(const float* __restrict__ W_tcn,
        const float* __restrict__ b_tcn,
        const float* __restrict__ W_out,
        const float* __restrict__ b_out,
        float* __restrict__ out) {
    extern __shared__ char dsm[];
    float4 (*sWt4)[64] = reinterpret_cast<float4(*)[64]>(dsm + SM3_WT);
    float4 (*su4)[8][32] = reinterpret_cast<float4(*)[8][32]>(dsm + SM3_SU);
    float*  sWtF = reinterpret_cast<float*>(dsm + SM3_WT);   // float view
    float*  sWoT = reinterpret_cast<float*>(dsm + SM3_WO);
    float*  sbt  = reinterpret_cast<float*>(dsm + SM3_BT);
    float*  sbo  = reinterpret_cast<float*>(dsm + SM3_BO);

    int tid = threadIdx.x;
    int w = tid >> 5, lane = tid & 31;

    // ---- coalesced W_tcn staging: warp handles rows o = w, w+17, ... ----
    // Each lane reads 6 floats of row o (flat f = lane + 32j), then scatters
    // the needed taps into sWt4[ip][o] = {f=6ip, 6ip+1, 6ip+3, 6ip+4}.
    for (int o = w; o < 64; o += K3_WARPS) {
        const float* wr = W_tcn + o * 192;
        #pragma unroll
        for (int j = 0; j < 6; j++) {
            int f = lane + 32 * j;
            float val = __ldg(wr + f);         // fully coalesced
            int ip = f / 6;
            int c  = f - ip * 6;               // 0..5
            // map c -> float4 component: 0->x,1->y,3->z,4->w; 2,5 unused
            int comp = (c == 0) ? 0 : (c == 1) ? 1 : (c == 3) ? 2 : (c == 4) ? 3 : -1;
            if (comp >= 0)
                sWtF[ip * 256 + o * 4 + comp] = val;
        }
    }
    // W_out transpose + biases
    for (int t = tid; t < 64 * PP; t += K3_THREADS) {
        float v = __ldg(W_out + t);            // coalesced
        int o = t / PP, p = t - o * PP;
        sWoT[p * 64 + o] = v;
    }
    if (tid < 64) sbt[tid] = b_tcn[tid];
    if (tid < PP) sbo[tid] = b_out[tid];
    __syncthreads();

    int nBase = (blockIdx.x * K3_WARPS + w) * K3_NPW;
    if (nBase >= NN) return;

    // ---- load relu'd agg, scatter to interleaved su4 ----
    int tap = (lane >> 4) & 1;
    int hb8 = (lane & 15) * 8;
    #pragma unroll
    for (int m = 0; m < K3_NPW; m++) {
        int node = nBase + m;
        int nd = node < NN ? node : NN - 1;
        const float4* ar = reinterpret_cast<const float4*>(g_agg + (size_t)nd * ROWF);
        float4 r0 = __ldg(ar + lane);        // b = 0 data
        float4 r1 = __ldg(ar + lane + 32);   // b = 1 data
        float* d0 = reinterpret_cast<float*>(&su4[w][m * 2 + 0][0]);
        float* d1 = reinterpret_cast<float*>(&su4[w][m * 2 + 1][0]);
        d0[hb8 + 0 + tap] = r0.x;  d0[hb8 + 2 + tap] = r0.y;
        d0[hb8 + 4 + tap] = r0.z;  d0[hb8 + 6 + tap] = r0.w;
        d1[hb8 + 0 + tap] = r1.x;  d1[hb8 + 2 + tap] = r1.y;
        d1[hb8 + 4 + tap] = r1.z;  d1[hb8 + 6 + tap] = r1.w;
    }
    __syncwarp();

    // ---- z-stage: 8 pairs, float4-packed weights ----
    float z0[8], z1[8];
    #pragma unroll
    for (int pp = 0; pp < 8; pp++) { z0[pp] = sbt[lane]; z1[pp] = sbt[lane + 32]; }
    #pragma unroll 4
    for (int ip = 0; ip < 32; ip++) {
        float4 wA = sWt4[ip][lane];
        float4 wB = sWt4[ip][lane + 32];
        #pragma unroll
        for (int pp = 0; pp < 8; pp++) {
            float4 u = su4[w][pp][ip];
            z0[pp] = fmaf(wA.x, u.x, fmaf(wA.y, u.y,
                     fmaf(wA.z, u.z, fmaf(wA.w, u.w, z0[pp]))));
            z1[pp] = fmaf(wB.x, u.x, fmaf(wB.y, u.y,
                     fmaf(wB.z, u.z, fmaf(wB.w, u.w, z1[pp]))));
        }
    }
    __syncwarp();
    #pragma unroll
    for (int pp = 0; pp < 8; pp++) {
        float* zf = reinterpret_cast<float*>(&su4[w][pp][0]);
        zf[lane]      = fmaxf(z0[pp], 0.0f);
        zf[lane + 32] = fmaxf(z1[pp], 0.0f);
    }
    __syncwarp();

    // ---- y-stage: 96 outputs (8 pairs x 12) in 3 lane-rounds ----
    #pragma unroll
    for (int r = 0; r < 3; r++) {
        int q = lane + r * 32;               // 0..95
        int pp = q / PP;
        int p  = q - pp * PP;
        float y = sbo[p];
        const float4* z4 = &su4[w][pp][0];
        const float4* w4 = reinterpret_cast<const float4*>(sWoT + p * 64);
        #pragma unroll 4
        for (int oc = 0; oc < 16; oc++) {
            float4 zz = z4[oc];
            float4 ww = w4[oc];
            y = fmaf(zz.x, ww.x, fmaf(zz.y, ww.y,
                fmaf(zz.z, ww.z, fmaf(zz.w, ww.w, y))));
        }
        int node = nBase + (pp >> 1);
        int b = pp & 1;
        if (node < NN)
            out[((size_t)b * PP + p) * NN + node] = y;
    }
}

// ---------------------------------------------------------------------------
extern "C" void kernel_launch(void* const* d_in, const int* in_sizes, int n_in,
                              void* d_out, int out_size) {
    const float* x     = (const float*)d_in[0];
    const int*   row   = (const int*)  d_in[1];
    const int*   col   = (const int*)  d_in[2];
    const float* vals  = (const float*)d_in[3];
    const float* W_in  = (const float*)d_in[4];
    const float* b_in  = (const float*)d_in[5];
    const float* W_tcn = (const float*)d_in[6];
    const float* b_tcn = (const float*)d_in[7];
    const float* W_out = (const float*)d_in[8];
    const float* b_out = (const float*)d_in[9];
    float* out = (float*)d_out;

    static bool attr_set = false;
    if (!attr_set) {
        cudaFuncSetAttribute(k_final,
                             cudaFuncAttributeMaxDynamicSharedMemorySize, SM3_TOT);
        attr_set = true;
    }

    k_proj_bin<<<1250, 256>>>(x, W_in, b_in, row, col, vals);
    k_gather<<<1250, 256>>>();
    k_final<<<148, K3_THREADS, SM3_TOT>>>(W_tcn, b_tcn, W_out, b_out, out);
}

// round 8
// speedup vs baseline: 1.4872x; 1.1743x over previous
#include <cuda_runtime.h>
#include <cuda_bf16.h>
#include <cstdint>

// Problem constants
#define NB 2        // B
#define LL 16       // L
#define NN 10000    // N
#define FIN 8
#define HH 64       // H
#define PP 12       // P
#define EE 80000    // E
// Only l = 14,15 feed out[:, :, -1]. Slot s = b*2 + (l-14); row = [n][s][64].
#define SLOTS 4
#define ROWF (SLOTS * HH)   // 256 floats per node row
#define CAP 64              // per-node edge bucket capacity (max deg ~35)

// Scratch
__device__ __align__(16) float g_h[(size_t)NN * ROWF];
__device__ __align__(16) float g_agg[(size_t)NN * ROWF];   // relu'd aggregate
__device__ int g_cnt[NN];                                  // zero-init; k_final cleans
__device__ __align__(8) int2 g_edge[(size_t)NN * CAP];     // {col, val_bits}

// ---------------------------------------------------------------------------
// K1: one warp per node: h[n,s,:] = relu(x[b,l,n,:]@W_in + b_in), s=0..3
//     (l in {14,15}); plus edge binning on the first EE threads.
// ---------------------------------------------------------------------------
__global__ void k_proj_bin(const float* __restrict__ x,
                           const float* __restrict__ W_in,
                           const float* __restrict__ b_in,
                           const int* __restrict__ row,
                           const int* __restrict__ col,
                           const float* __restrict__ vals) {
    __shared__ float sW[FIN * HH];
    __shared__ float sb[HH];
    int tid = threadIdx.x;
    int gid = blockIdx.x * blockDim.x + tid;

    if (gid < EE) {
        int r = __ldg(row + gid);
        int rank = atomicAdd(&g_cnt[r], 1);
        if (rank < CAP)
            g_edge[(size_t)r * CAP + rank] =
                make_int2(__ldg(col + gid), __float_as_int(__ldg(vals + gid)));
    }

    for (int i = tid; i < FIN * HH; i += blockDim.x) sW[i] = W_in[i];
    if (tid < HH) sb[tid] = b_in[tid];
    __syncthreads();

    int n = blockIdx.x * 8 + (tid >> 5);   // exactly 10000
    int lane = tid & 31;

    #pragma unroll
    for (int s = 0; s < SLOTS; s++) {
        int b = s >> 1;
        int l = 14 + (s & 1);
        const float4* xr = reinterpret_cast<const float4*>(
            x + (((size_t)b * LL + l) * NN + n) * FIN);
        float4 x0 = __ldg(xr);       // warp-broadcast 32B row
        float4 x1 = __ldg(xr + 1);
        float xv[8] = {x0.x, x0.y, x0.z, x0.w, x1.x, x1.y, x1.z, x1.w};

        float* hrow = g_h + ((size_t)n * SLOTS + s) * HH;
        #pragma unroll
        for (int rep = 0; rep < 2; rep++) {
            int hh = lane + rep * 32;
            float acc = sb[hh];
            #pragma unroll
            for (int f = 0; f < 8; f++) acc = fmaf(xv[f], sW[f * HH + hh], acc);
            hrow[hh] = fmaxf(acc, 0.0f);
        }
    }
}

// ---------------------------------------------------------------------------
// K2: gather v3 — 2 warps per node row (20000 warps). Warp (n, half) owns
// 512B of the 1KB row. Per edge: uniform LDG.64 of the edge record (L1-hot,
// 16 edges/line, no shfl), one LDG.128 row-half, 16 FMA. 4-edge unroll with
// branch-free padding -> 4 independent row loads in flight. ~40 regs.
// ---------------------------------------------------------------------------
__global__ void k_gather() {
    int w = blockIdx.x * 8 + (threadIdx.x >> 5);   // exactly 20000 warps
    int lane = threadIdx.x & 31;
    int n    = w >> 1;
    int half = w & 1;

    int deg = g_cnt[n];
    if (deg > CAP) deg = CAP;
    const int2* ep = g_edge + (size_t)n * CAP;
    const float4* hbase = reinterpret_cast<const float4*>(g_h) + half * 32;

    float4 a = make_float4(0.f, 0.f, 0.f, 0.f);

    for (int k = 0; k < deg; k += 4) {
        int   c[4];
        float v[4];
        #pragma unroll
        for (int j = 0; j < 4; j++) {
            int kk = k + j < deg ? k + j : deg - 1;   // pad with last edge
            int2 e = __ldg(ep + kk);                  // uniform, L1-hot
            c[j] = e.x;
            v[j] = (k + j < deg) ? __int_as_float(e.y) : 0.0f;
        }
        float4 h[4];
        #pragma unroll
        for (int j = 0; j < 4; j++)
            h[j] = __ldg(hbase + (size_t)c[j] * 64 + lane);  // 64 float4/row
        #pragma unroll
        for (int j = 0; j < 4; j++) {
            a.x = fmaf(h[j].x, v[j], a.x);
            a.y = fmaf(h[j].y, v[j], a.y);
            a.z = fmaf(h[j].z, v[j], a.z);
            a.w = fmaf(h[j].w, v[j], a.w);
        }
    }

    float4* ap = reinterpret_cast<float4*>(g_agg) + (size_t)n * 64 + half * 32;
    ap[lane] = make_float4(fmaxf(a.x, 0.f), fmaxf(a.y, 0.f),
                           fmaxf(a.z, 0.f), fmaxf(a.w, 0.f));
}

// ---------------------------------------------------------------------------
// K3: final stage — persistent: grid 148, 17 warps, 4 nodes/warp.
// Also zeroes g_cnt for the next graph replay (one coalesced store).
// ---------------------------------------------------------------------------
#define K3_WARPS 17
#define K3_THREADS (K3_WARPS * 32)            // 544
#define K3_NPW 4

#define SM3_WT 0
#define SM3_SU (SM3_WT + 32 * 64 * 16)                     // 32768
#define SM3_WO (SM3_SU + K3_WARPS * 8 * 32 * 16)           // +69632 = 102400
#define SM3_BT (SM3_WO + PP * 64 * 4)                      // +3072  = 105472
#define SM3_BO (SM3_BT + 64 * 4)                           // +256   = 105728
#define SM3_TOT (SM3_BO + 64)                              //        = 105792

__global__ void __launch_bounds__(K3_THREADS, 1)
k_final(const float* __restrict__ W_tcn,
        const float* __restrict__ b_tcn,
        const float* __restrict__ W_out,
        const float* __restrict__ b_out,
        float* __restrict__ out) {
    extern __shared__ char dsm[];
    float4 (*sWt4)[64] = reinterpret_cast<float4(*)[64]>(dsm + SM3_WT);
    float4 (*su4)[8][32] = reinterpret_cast<float4(*)[8][32]>(dsm + SM3_SU);
    float*  sWtF = reinterpret_cast<float*>(dsm + SM3_WT);   // float view
    float*  sWoT = reinterpret_cast<float*>(dsm + SM3_WO);
    float*  sbt  = reinterpret_cast<float*>(dsm + SM3_BT);
    float*  sbo  = reinterpret_cast<float*>(dsm + SM3_BO);

    int tid = threadIdx.x;
    int w = tid >> 5, lane = tid & 31;

    // zero g_cnt for next replay (148*544 = 80512 >= NN)
    {
        int t = blockIdx.x * K3_THREADS + tid;
        if (t < NN) g_cnt[t] = 0;
    }

    // ---- coalesced W_tcn staging: warp handles rows o = w, w+17, ... ----
    for (int o = w; o < 64; o += K3_WARPS) {
        const float* wr = W_tcn + o * 192;
        #pragma unroll
        for (int j = 0; j < 6; j++) {
            int f = lane + 32 * j;
            float val = __ldg(wr + f);         // fully coalesced
            int ip = f / 6;
            int c  = f - ip * 6;               // 0..5
            int comp = (c == 0) ? 0 : (c == 1) ? 1 : (c == 3) ? 2 : (c == 4) ? 3 : -1;
            if (comp >= 0)
                sWtF[ip * 256 + o * 4 + comp] = val;
        }
    }
    for (int t = tid; t < 64 * PP; t += K3_THREADS) {
        float v = __ldg(W_out + t);            // coalesced
        int o = t / PP, p = t - o * PP;
        sWoT[p * 64 + o] = v;
    }
    if (tid < 64) sbt[tid] = b_tcn[tid];
    if (tid < PP) sbo[tid] = b_out[tid];
    __syncthreads();

    int nBase = (blockIdx.x * K3_WARPS + w) * K3_NPW;
    if (nBase >= NN) return;

    // ---- load relu'd agg, scatter to interleaved su4 ----
    int tap = (lane >> 4) & 1;
    int hb8 = (lane & 15) * 8;
    #pragma unroll
    for (int m = 0; m < K3_NPW; m++) {
        int node = nBase + m;
        int nd = node < NN ? node : NN - 1;
        const float4* ar = reinterpret_cast<const float4*>(g_agg + (size_t)nd * ROWF);
        float4 r0 = __ldg(ar + lane);        // b = 0 data
        float4 r1 = __ldg(ar + lane + 32);   // b = 1 data
        float* d0 = reinterpret_cast<float*>(&su4[w][m * 2 + 0][0]);
        float* d1 = reinterpret_cast<float*>(&su4[w][m * 2 + 1][0]);
        d0[hb8 + 0 + tap] = r0.x;  d0[hb8 + 2 + tap] = r0.y;
        d0[hb8 + 4 + tap] = r0.z;  d0[hb8 + 6 + tap] = r0.w;
        d1[hb8 + 0 + tap] = r1.x;  d1[hb8 + 2 + tap] = r1.y;
        d1[hb8 + 4 + tap] = r1.z;  d1[hb8 + 6 + tap] = r1.w;
    }
    __syncwarp();

    // ---- z-stage: 8 pairs, float4-packed weights ----
    float z0[8], z1[8];
    #pragma unroll
    for (int pp = 0; pp < 8; pp++) { z0[pp] = sbt[lane]; z1[pp] = sbt[lane + 32]; }
    #pragma unroll 4
    for (int ip = 0; ip < 32; ip++) {
        float4 wA = sWt4[ip][lane];
        float4 wB = sWt4[ip][lane + 32];
        #pragma unroll
        for (int pp = 0; pp < 8; pp++) {
            float4 u = su4[w][pp][ip];
            z0[pp] = fmaf(wA.x, u.x, fmaf(wA.y, u.y,
                     fmaf(wA.z, u.z, fmaf(wA.w, u.w, z0[pp]))));
            z1[pp] = fmaf(wB.x, u.x, fmaf(wB.y, u.y,
                     fmaf(wB.z, u.z, fmaf(wB.w, u.w, z1[pp]))));
        }
    }
    __syncwarp();
    #pragma unroll
    for (int pp = 0; pp < 8; pp++) {
        float* zf = reinterpret_cast<float*>(&su4[w][pp][0]);
        zf[lane]      = fmaxf(z0[pp], 0.0f);
        zf[lane + 32] = fmaxf(z1[pp], 0.0f);
    }
    __syncwarp();

    // ---- y-stage: 96 outputs (8 pairs x 12) in 3 lane-rounds ----
    #pragma unroll
    for (int r = 0; r < 3; r++) {
        int q = lane + r * 32;               // 0..95
        int pp = q / PP;
        int p  = q - pp * PP;
        float y = sbo[p];
        const float4* z4 = &su4[w][pp][0];
        const float4* w4 = reinterpret_cast<const float4*>(sWoT + p * 64);
        #pragma unroll 4
        for (int oc = 0; oc < 16; oc++) {
            float4 zz = z4[oc];
            float4 ww = w4[oc];
            y = fmaf(zz.x, ww.x, fmaf(zz.y, ww.y,
                fmaf(zz.z, ww.z, fmaf(zz.w, ww.w, y))));
        }
        int node = nBase + (pp >> 1);
        int b = pp & 1;
        if (node < NN)
            out[((size_t)b * PP + p) * NN + node] = y;
    }
}

// ---------------------------------------------------------------------------
extern "C" void kernel_launch(void* const* d_in, const int* in_sizes, int n_in,
                              void* d_out, int out_size) {
    const float* x     = (const float*)d_in[0];
    const int*   row   = (const int*)  d_in[1];
    const int*   col   = (const int*)  d_in[2];
    const float* vals  = (const float*)d_in[3];
    const float* W_in  = (const float*)d_in[4];
    const float* b_in  = (const float*)d_in[5];
    const float* W_tcn = (const float*)d_in[6];
    const float* b_tcn = (const float*)d_in[7];
    const float* W_out = (const float*)d_in[8];
    const float* b_out = (const float*)d_in[9];
    float* out = (float*)d_out;

    static bool attr_set = false;
    if (!attr_set) {
        cudaFuncSetAttribute(k_final,
                             cudaFuncAttributeMaxDynamicSharedMemorySize, SM3_TOT);
        attr_set = true;
    }

    k_proj_bin<<<1250, 256>>>(x, W_in, b_in, row, col, vals);
    k_gather<<<2500, 256>>>();
    k_final<<<148, K3_THREADS, SM3_TOT>>>(W_tcn, b_tcn, W_out, b_out, out);
}